// round 10
// baseline (speedup 1.0000x reference)
#include <cuda_runtime.h>
#include <math.h>

namespace {

constexpr int BS    = 16;
constexpr int NGT   = 20;
constexpr int NA    = 3;
constexpr int GS    = 76;
constexpr int NC    = 80;
constexpr int NATTR = 5 + NC;           // 85
constexpr int PLANE = GS * GS;          // 5776
constexpr int TOTAL_CELLS = BS * NA * GS * GS;  // 277248

constexpr int BPB   = 10;               // blocks per batch
constexpr int GPB   = NGT / BPB;        // 2 GT-warps per block
constexpr int NBLK  = BS * BPB;         // 160 blocks
constexpr int NTHR  = 64;               // 2 warps (>= 60 probe threads)
constexpr unsigned FULL = 0xffffffffu;

__device__ float        g_part[7 * NBLK];    // per-block partials
__device__ unsigned int g_tickets;           // zero-init; reset by last block

__device__ __forceinline__ float sigmoidf(float v) {
    return 1.0f / (1.0f + expf(-v));
}
__device__ __forceinline__ float anc_w(int a) {
    return (a == 0) ? 1.25f : (a == 1) ? 2.0f : 4.125f;
}
__device__ __forceinline__ float anc_h(int a) {
    return (a == 0) ? 1.625f : (a == 1) ? 3.75f : 2.875f;
}

__global__ __launch_bounds__(NTHR)
void yolo_fused_kernel(const float* __restrict__ x,
                       const float* __restrict__ yt,
                       float* __restrict__ out)
{
    __shared__ float s_iou[NGT * NA];       // 60 probe IoUs (s_iou[0] reused as tail flag)
    __shared__ float s_gx[NGT], s_gy[NGT], s_gw[NGT], s_gh[NGT];
    __shared__ int   s_gi[NGT], s_gj[NGT], s_cls[NGT];
    __shared__ int   s_lin[NGT], s_bestA[NGT];
    __shared__ float s_bestI[NGT];
    __shared__ float s_red[7][GPB];

    const int t    = threadIdx.x;
    const int b    = blockIdx.x / BPB;      // batch 0..15
    const int sub  = blockIdx.x - b * BPB;  // 0..9
    const int wid  = t >> 5;                // warp 0..1
    const int lane = t & 31;

    // ---- Phase A: threads 0..59 probe (GT pg, anchor pa) -----------------
    if (t < NGT * NA) {
        const int pg = t / 3;
        const int pa = t - pg * 3;

        const float* gp = yt + ((size_t)b * NGT + pg) * 5;
        const float gx = gp[0] * (float)GS;
        const float gy = gp[1] * (float)GS;
        const float gw = gp[2] * (float)GS;
        const float gh = gp[3] * (float)GS;

        const int gi = min(max((int)gx, 0), GS - 1);
        const int gj = min(max((int)gy, 0), GS - 1);

        if (pa == 0) {
            s_gx[pg] = gx;  s_gy[pg] = gy;
            s_gw[pg] = gw;  s_gh[pg] = gh;
            s_gi[pg] = gi;  s_gj[pg] = gj;
            s_cls[pg] = (int)gp[4];
        }

        const float gx1 = gx - gw / 2.0f, gy1 = gy - gh / 2.0f;
        const float gx2 = gx + gw / 2.0f, gy2 = gy + gh / 2.0f;
        const float area_g = (gx2 - gx1) * (gy2 - gy1);

        const float* xp = x + (size_t)(b * NA + pa) * NATTR * PLANE
                            + (size_t)gj * GS + gi;
        const float txp = xp[0];
        const float typ = xp[PLANE];
        const float twp = xp[2 * PLANE];
        const float thp = xp[3 * PLANE];

        const float bx = sigmoidf(txp) + (float)gi;
        const float by = sigmoidf(typ) + (float)gj;
        const float bw = expf(twp) * anc_w(pa);
        const float bh = expf(thp) * anc_h(pa);

        const float px1 = bx - bw / 2.0f, py1 = by - bh / 2.0f;
        const float px2 = bx + bw / 2.0f, py2 = by + bh / 2.0f;

        const float ix1 = fmaxf(px1, gx1), iy1 = fmaxf(py1, gy1);
        const float ix2 = fminf(px2, gx2), iy2 = fminf(py2, gy2);
        const float inter = fmaxf(ix2 - ix1, 0.0f) * fmaxf(iy2 - iy1, 0.0f);
        const float area_p = (px2 - px1) * (py2 - py1);
        s_iou[t] = inter / (area_p + area_g - inter + 1e-16f);
    }
    __syncthreads();

    // ---- argmax per GT (threads 0..19); first max wins -> strict > -------
    if (t < NGT) {
        const float i0 = s_iou[3 * t + 0];
        const float i1 = s_iou[3 * t + 1];
        const float i2 = s_iou[3 * t + 2];
        int   bestA = 0;
        float bestI = i0;
        if (i1 > bestI) { bestI = i1; bestA = 1; }
        if (i2 > bestI) { bestI = i2; bestA = 2; }
        s_bestA[t] = bestA;
        s_bestI[t] = bestI;
        s_lin[t]   = ((b * NA + bestA) * GS + s_gj[t]) * GS + s_gi[t];
    }
    __syncthreads();

    // ---- Phase B: warp w handles GT g = sub*GPB + w ----------------------
    const int g      = sub * GPB + wid;
    const int linM   = s_lin[g];
    const int bestAM = s_bestA[g];
    const float bestIM = s_bestI[g];
    const int clsM   = s_cls[g];

    // issue phase-2 loads immediately (<=4 per lane, all independent)
    const float* base = x + (size_t)(linM / PLANE) * NATTR * PLANE
                          + (linM % PLANE);
    float attr = 0.0f;
    if (lane < 5)       attr = base[(size_t)lane * PLANE];
    else if (lane == 5) attr = base[(size_t)(5 + clsM) * PLANE];

    const float v0 = base[(size_t)(5 + lane) * PLANE];
    const float v1 = base[(size_t)(5 + lane + 32) * PLANE];
    const float v2 = (lane < NC - 64) ? base[(size_t)(5 + lane + 64) * PLANE]
                                      : -INFINITY;

    // dedup: JAX scatter .set -> last flat index wins (ballot over smem)
    const bool dupL = (lane > g) && (lane < NGT) && (s_lin[lane] == linM);
    const unsigned dmask = __ballot_sync(FULL, dupL);

    float lx = 0.f, ly = 0.f, lw = 0.f, lh = 0.f;
    float lcls = 0.f, lconf = 0.f, fwin = 0.f;

    if (dmask == 0u) {   // winner
        fwin = 1.0f;

        float m = fmaxf(fmaxf(v0, v1), v2);
        #pragma unroll
        for (int o = 16; o > 0; o >>= 1)
            m = fmaxf(m, __shfl_xor_sync(FULL, m, o));

        float s = expf(v0 - m) + expf(v1 - m) +
                  ((lane < NC - 64) ? expf(v2 - m) : 0.0f);
        #pragma unroll
        for (int o = 16; o > 0; o >>= 1)
            s += __shfl_xor_sync(FULL, s, o);

        const float tx = __shfl_sync(FULL, attr, 0);
        const float ty = __shfl_sync(FULL, attr, 1);
        const float tw = __shfl_sync(FULL, attr, 2);
        const float th = __shfl_sync(FULL, attr, 3);
        const float cf = __shfl_sync(FULL, attr, 4);
        const float pk = __shfl_sync(FULL, attr, 5);

        const float dx = sigmoidf(tx) - (s_gx[g] - (float)s_gi[g]);
        const float dy = sigmoidf(ty) - (s_gy[g] - (float)s_gj[g]);
        const float dw = tw - logf(s_gw[g] / anc_w(bestAM));
        const float dh = th - logf(s_gh[g] / anc_h(bestAM));
        const float dc = sigmoidf(cf) * 5.0f - bestIM * 5.0f;

        lx = dx * dx; ly = dy * dy; lw = dw * dw; lh = dh * dh;
        lconf = dc * dc;
        lcls  = (m + logf(s)) - pk;
    }

    // ---- block partials (plain STG, no contended float atomics) ----------
    if (lane == 0) {
        s_red[0][wid] = lx;   s_red[1][wid] = ly;
        s_red[2][wid] = lw;   s_red[3][wid] = lh;
        s_red[4][wid] = lcls; s_red[5][wid] = lconf;
        s_red[6][wid] = fwin;
    }
    __syncthreads();

    if (t < 7) {
        float s = 0.0f;
        #pragma unroll
        for (int w = 0; w < GPB; w++) s += s_red[t][w];
        g_part[t * NBLK + blockIdx.x] = s;
    }
    __syncthreads();

    if (t == 0) {
        __threadfence();
        const unsigned old = atomicAdd(&g_tickets, 1u);
        // flag completion for the whole block via smem
        s_iou[0] = (old == NBLK - 1) ? 1.0f : 0.0f;
    }
    __syncthreads();

    // ---- last block: warp 0 reduces 7 x 160 partials ---------------------
    if (s_iou[0] != 0.0f && wid == 0) {
        __threadfence();
        float acc[7] = {0, 0, 0, 0, 0, 0, 0};
        for (int blk = lane; blk < NBLK; blk += 32) {
            #pragma unroll
            for (int i = 0; i < 7; i++)
                acc[i] += g_part[i * NBLK + blk];
        }
        #pragma unroll
        for (int i = 0; i < 7; i++) {
            #pragma unroll
            for (int o = 16; o > 0; o >>= 1)
                acc[i] += __shfl_xor_sync(FULL, acc[i], o);
        }
        if (lane == 0) {
            const int n_obj = (int)(acc[6] + 0.5f);
            out[0] = acc[0];  out[1] = acc[1];
            out[2] = acc[2];  out[3] = acc[3];
            out[4] = (float)((double)(TOTAL_CELLS - n_obj)
                             * (double)logf(80.0f) + (double)acc[4]);
            out[5] = acc[5];
            g_tickets = 0u;          // reset for next graph replay
            __threadfence();
        }
    }
}

} // namespace

extern "C" void kernel_launch(void* const* d_in, const int* in_sizes, int n_in,
                              void* d_out, int out_size)
{
    const float* x  = (const float*)d_in[0];   // (16, 255, 76, 76) f32
    const float* yt = (const float*)d_in[1];   // (16, 20, 5) f32
    float* out = (float*)d_out;                // 6 floats

    yolo_fused_kernel<<<NBLK, NTHR>>>(x, yt, out);
}

// round 11
// speedup vs baseline: 1.0299x; 1.0299x over previous
#include <cuda_runtime.h>
#include <math.h>

namespace {

constexpr int BS    = 16;
constexpr int NGT   = 20;
constexpr int NA    = 3;
constexpr int GS    = 76;
constexpr int NC    = 80;
constexpr int NATTR = 5 + NC;           // 85
constexpr int PLANE = GS * GS;          // 5776
constexpr int TOTAL_CELLS = BS * NA * GS * GS;  // 277248

constexpr int BPB   = 10;               // blocks per batch
constexpr int GPB   = NGT / BPB;        // 2 GT-warps per block
constexpr int NBLK  = BS * BPB;         // 160 blocks
constexpr int NTHR  = 64;               // 2 warps (>= 60 probe threads)
constexpr unsigned FULL = 0xffffffffu;

__device__ float        g_part[7 * NBLK];    // per-block partials
__device__ unsigned int g_tickets;           // zero-init; reset by last block

__device__ __forceinline__ float sigmoidf(float v) {
    return 1.0f / (1.0f + expf(-v));
}
__device__ __forceinline__ float anc_w(int a) {
    return (a == 0) ? 1.25f : (a == 1) ? 2.0f : 4.125f;
}
__device__ __forceinline__ float anc_h(int a) {
    return (a == 0) ? 1.625f : (a == 1) ? 3.75f : 2.875f;
}

__global__ __launch_bounds__(NTHR)
void yolo_fused_kernel(const float* __restrict__ x,
                       const float* __restrict__ yt,
                       float* __restrict__ out)
{
    __shared__ float s_iou[NGT * NA];       // 60 probe IoUs (s_iou[0] reused as tail flag)
    __shared__ float s_gx[NGT], s_gy[NGT], s_gw[NGT], s_gh[NGT];
    __shared__ int   s_gi[NGT], s_gj[NGT], s_cls[NGT];
    __shared__ int   s_lin[NGT], s_bestA[NGT];
    __shared__ float s_bestI[NGT];
    __shared__ float s_red[7][GPB];

    const int t    = threadIdx.x;
    const int b    = blockIdx.x / BPB;      // batch 0..15
    const int sub  = blockIdx.x - b * BPB;  // 0..9
    const int wid  = t >> 5;                // warp 0..1
    const int lane = t & 31;

    // ---- Phase A: threads 0..59 probe (GT pg, anchor pa) -----------------
    if (t < NGT * NA) {
        const int pg = t / 3;
        const int pa = t - pg * 3;

        const float* gp = yt + ((size_t)b * NGT + pg) * 5;
        const float gx = gp[0] * (float)GS;
        const float gy = gp[1] * (float)GS;
        const float gw = gp[2] * (float)GS;
        const float gh = gp[3] * (float)GS;

        const int gi = min(max((int)gx, 0), GS - 1);
        const int gj = min(max((int)gy, 0), GS - 1);

        if (pa == 0) {
            s_gx[pg] = gx;  s_gy[pg] = gy;
            s_gw[pg] = gw;  s_gh[pg] = gh;
            s_gi[pg] = gi;  s_gj[pg] = gj;
            s_cls[pg] = (int)gp[4];
        }

        const float gx1 = gx - gw / 2.0f, gy1 = gy - gh / 2.0f;
        const float gx2 = gx + gw / 2.0f, gy2 = gy + gh / 2.0f;
        const float area_g = (gx2 - gx1) * (gy2 - gy1);

        const float* xp = x + (size_t)(b * NA + pa) * NATTR * PLANE
                            + (size_t)gj * GS + gi;
        const float txp = xp[0];
        const float typ = xp[PLANE];
        const float twp = xp[2 * PLANE];
        const float thp = xp[3 * PLANE];

        const float bx = sigmoidf(txp) + (float)gi;
        const float by = sigmoidf(typ) + (float)gj;
        const float bw = expf(twp) * anc_w(pa);
        const float bh = expf(thp) * anc_h(pa);

        const float px1 = bx - bw / 2.0f, py1 = by - bh / 2.0f;
        const float px2 = bx + bw / 2.0f, py2 = by + bh / 2.0f;

        const float ix1 = fmaxf(px1, gx1), iy1 = fmaxf(py1, gy1);
        const float ix2 = fminf(px2, gx2), iy2 = fminf(py2, gy2);
        const float inter = fmaxf(ix2 - ix1, 0.0f) * fmaxf(iy2 - iy1, 0.0f);
        const float area_p = (px2 - px1) * (py2 - py1);
        s_iou[t] = inter / (area_p + area_g - inter + 1e-16f);
    }
    __syncthreads();

    // ---- argmax per GT (threads 0..19); first max wins -> strict > -------
    if (t < NGT) {
        const float i0 = s_iou[3 * t + 0];
        const float i1 = s_iou[3 * t + 1];
        const float i2 = s_iou[3 * t + 2];
        int   bestA = 0;
        float bestI = i0;
        if (i1 > bestI) { bestI = i1; bestA = 1; }
        if (i2 > bestI) { bestI = i2; bestA = 2; }
        s_bestA[t] = bestA;
        s_bestI[t] = bestI;
        s_lin[t]   = ((b * NA + bestA) * GS + s_gj[t]) * GS + s_gi[t];
    }
    __syncthreads();

    // ---- Phase B: warp w handles GT g = sub*GPB + w ----------------------
    const int g      = sub * GPB + wid;
    const int linM   = s_lin[g];
    const int bestAM = s_bestA[g];
    const float bestIM = s_bestI[g];
    const int clsM   = s_cls[g];

    // issue phase-2 loads immediately (<=4 per lane, all independent)
    const float* base = x + (size_t)(linM / PLANE) * NATTR * PLANE
                          + (linM % PLANE);
    float attr = 0.0f;
    if (lane < 5)       attr = base[(size_t)lane * PLANE];
    else if (lane == 5) attr = base[(size_t)(5 + clsM) * PLANE];

    const float v0 = base[(size_t)(5 + lane) * PLANE];
    const float v1 = base[(size_t)(5 + lane + 32) * PLANE];
    const float v2 = (lane < NC - 64) ? base[(size_t)(5 + lane + 64) * PLANE]
                                      : -INFINITY;

    // dedup: JAX scatter .set -> last flat index wins (ballot over smem)
    const bool dupL = (lane > g) && (lane < NGT) && (s_lin[lane] == linM);
    const unsigned dmask = __ballot_sync(FULL, dupL);

    float lx = 0.f, ly = 0.f, lw = 0.f, lh = 0.f;
    float lcls = 0.f, lconf = 0.f, fwin = 0.f;

    if (dmask == 0u) {   // winner
        fwin = 1.0f;

        float m = fmaxf(fmaxf(v0, v1), v2);
        #pragma unroll
        for (int o = 16; o > 0; o >>= 1)
            m = fmaxf(m, __shfl_xor_sync(FULL, m, o));

        float s = expf(v0 - m) + expf(v1 - m) +
                  ((lane < NC - 64) ? expf(v2 - m) : 0.0f);
        #pragma unroll
        for (int o = 16; o > 0; o >>= 1)
            s += __shfl_xor_sync(FULL, s, o);

        const float tx = __shfl_sync(FULL, attr, 0);
        const float ty = __shfl_sync(FULL, attr, 1);
        const float tw = __shfl_sync(FULL, attr, 2);
        const float th = __shfl_sync(FULL, attr, 3);
        const float cf = __shfl_sync(FULL, attr, 4);
        const float pk = __shfl_sync(FULL, attr, 5);

        const float dx = sigmoidf(tx) - (s_gx[g] - (float)s_gi[g]);
        const float dy = sigmoidf(ty) - (s_gy[g] - (float)s_gj[g]);
        const float dw = tw - logf(s_gw[g] / anc_w(bestAM));
        const float dh = th - logf(s_gh[g] / anc_h(bestAM));
        const float dc = sigmoidf(cf) * 5.0f - bestIM * 5.0f;

        lx = dx * dx; ly = dy * dy; lw = dw * dw; lh = dh * dh;
        lconf = dc * dc;
        lcls  = (m + logf(s)) - pk;
    }

    // ---- block partials (plain STG, no contended float atomics) ----------
    if (lane == 0) {
        s_red[0][wid] = lx;   s_red[1][wid] = ly;
        s_red[2][wid] = lw;   s_red[3][wid] = lh;
        s_red[4][wid] = lcls; s_red[5][wid] = lconf;
        s_red[6][wid] = fwin;
    }
    __syncthreads();

    if (t < 7) {
        float s = 0.0f;
        #pragma unroll
        for (int w = 0; w < GPB; w++) s += s_red[t][w];
        g_part[t * NBLK + blockIdx.x] = s;
    }
    __syncthreads();

    if (t == 0) {
        __threadfence();
        const unsigned old = atomicAdd(&g_tickets, 1u);
        // flag completion for the whole block via smem
        s_iou[0] = (old == NBLK - 1) ? 1.0f : 0.0f;
    }
    __syncthreads();

    // ---- last block: warp 0 reduces 7 x 160 partials ---------------------
    if (s_iou[0] != 0.0f && wid == 0) {
        __threadfence();
        float acc[7] = {0, 0, 0, 0, 0, 0, 0};
        for (int blk = lane; blk < NBLK; blk += 32) {
            #pragma unroll
            for (int i = 0; i < 7; i++)
                acc[i] += g_part[i * NBLK + blk];
        }
        #pragma unroll
        for (int i = 0; i < 7; i++) {
            #pragma unroll
            for (int o = 16; o > 0; o >>= 1)
                acc[i] += __shfl_xor_sync(FULL, acc[i], o);
        }
        if (lane == 0) {
            const int n_obj = (int)(acc[6] + 0.5f);
            out[0] = acc[0];  out[1] = acc[1];
            out[2] = acc[2];  out[3] = acc[3];
            out[4] = (float)((double)(TOTAL_CELLS - n_obj)
                             * (double)logf(80.0f) + (double)acc[4]);
            out[5] = acc[5];
            g_tickets = 0u;          // reset for next graph replay
            __threadfence();
        }
    }
}

} // namespace

extern "C" void kernel_launch(void* const* d_in, const int* in_sizes, int n_in,
                              void* d_out, int out_size)
{
    const float* x  = (const float*)d_in[0];   // (16, 255, 76, 76) f32
    const float* yt = (const float*)d_in[1];   // (16, 20, 5) f32
    float* out = (float*)d_out;                // 6 floats

    yolo_fused_kernel<<<NBLK, NTHR>>>(x, yt, out);
}